// round 4
// baseline (speedup 1.0000x reference)
#include <cuda_runtime.h>
#include <cstdint>
#include <cstddef>

// Problem constants (fixed by the reference)
#define D_   256
#define NQ_  1024     // B * Q_PER_IMAGE
#define B_   4
#define NF_  65536    // feats per image
#define KDIM 256

// MLP ping-pong scratch (__device__ globals: the sanctioned no-alloc path)
__device__ float g_buf1[NQ_ * D_];
__device__ float g_buf2[NQ_ * D_];

// ---------------------------------------------------------------------------
// tf32 mma.sync GEMM:  C[256 x 128] per CTA = A[256 x 256] @ B[128 x 256]^T
//  - B (n-rows, k-cols) converted to tf32 ONCE into SMEM, k-pair permuted so
//    each fragment pair (k+t, k+t+4) is one aligned LDS.64, no cvt in loop.
//  - A streamed via cp.async double buffer (BK=16), cvt.rna at fragment load.
//  - 8 warps as 4(m) x 2(n); warp tile 64x64 = 4 m16 x 8 n8 = 32 MMAs / k8.
// ---------------------------------------------------------------------------
#define BM 256
#define BN 128
#define BK 16
#define KSTEPS (KDIM / BK)   // 16
#define BS_STRIDE 264        // words per B row (conflict-free for LDS.64)
#define AS_STRIDE 20         // words per A row (conflict-free scalar LDS)

#define BS_WORDS (BN * BS_STRIDE)                 // 33792
#define AS_WORDS (2 * BM * AS_STRIDE)             // 10240
#define DYN_SMEM ((BS_WORDS + AS_WORDS) * 4)      // 176128 B

__device__ __forceinline__ uint32_t f2tf32(float x) {
    uint32_t r;
    asm("cvt.rna.tf32.f32 %0, %1;" : "=r"(r) : "f"(x));
    return r;
}
__device__ __forceinline__ void mma_tf32(float c[4], const uint32_t a[4], const uint32_t b[2]) {
    asm volatile(
        "mma.sync.aligned.m16n8k8.row.col.f32.tf32.tf32.f32 "
        "{%0,%1,%2,%3},{%4,%5,%6,%7},{%8,%9},{%0,%1,%2,%3};"
        : "+f"(c[0]), "+f"(c[1]), "+f"(c[2]), "+f"(c[3])
        : "r"(a[0]), "r"(a[1]), "r"(a[2]), "r"(a[3]), "r"(b[0]), "r"(b[1]));
}
// permuted k index: pairs (k, k+4) within each 8-group land adjacent
__device__ __forceinline__ int permk(int k) {
    return (k & ~7) | ((k & 3) << 1) | ((k >> 2) & 1);
}

__global__ __launch_bounds__(256)
void gemm_mma(const float* __restrict__ A, const float* __restrict__ B,
              float* __restrict__ C, const float* __restrict__ bias, int relu,
              long long aStride, long long bStride, long long cStride)
{
    extern __shared__ uint32_t smem[];
    uint32_t* Bs = smem;                         // [BN][BS_STRIDE] tf32, permuted
    float*    As = (float*)(smem + BS_WORDS);    // [2][BM][AS_STRIDE] raw fp32
    __shared__ float s_bias[BN];

    const int tid = threadIdx.x;
    const int w = tid >> 5, lane = tid & 31;
    const int g = lane >> 2, t = lane & 3;
    const int wm = (w & 3) * 64;     // warp m origin
    const int wn = (w >> 2) * 64;    // warp n origin

    const int nb = blockIdx.x;       // n-inner: both n-blocks share the A tile in L2
    const int mb = blockIdx.y;
    const long long bb = blockIdx.z;

    const float* Ab = A + bb * aStride + (size_t)mb * BM * KDIM;
    const float* Bb = B + bb * bStride + (size_t)nb * BN * KDIM;
    float*       Cb = C + bb * cStride + (size_t)mb * BM * 256 + (size_t)nb * BN;

    if (bias && tid < BN) s_bias[tid] = bias[nb * BN + tid];

    // ---- issue A chunk kt into buffer buf (cp.async, 16B each) ----
    auto issueA = [&](int kt, int buf) {
        const int c4 = (tid & 3) * 4;
        const int k0 = kt * BK + c4;
#pragma unroll
        for (int p = 0; p < 4; p++) {
            int r = (tid >> 2) + p * 64;
            uint32_t dst = (uint32_t)__cvta_generic_to_shared(
                &As[(size_t)buf * BM * AS_STRIDE + r * AS_STRIDE + c4]);
            const float* src = Ab + (size_t)r * KDIM + k0;
            asm volatile("cp.async.cg.shared.global [%0], [%1], 16;" :: "r"(dst), "l"(src));
        }
    };

    issueA(0, 0);
    asm volatile("cp.async.commit_group;");
    issueA(1, 1);
    asm volatile("cp.async.commit_group;");

    // ---- B preload: global fp32 -> tf32 -> permuted SMEM (once) ----
#pragma unroll 4
    for (int i = 0; i < (BN * KDIM / 4) / 256; i++) {   // 32 iters, one float4 each
        int idx = tid + i * 256;
        int r = idx >> 6;            // 64 float4 per row
        int k0 = (idx & 63) * 4;
        float4 v = *(const float4*)&Bb[(size_t)r * KDIM + k0];
        uint32_t* row = &Bs[r * BS_STRIDE];
        row[permk(k0 + 0)] = f2tf32(v.x);
        row[permk(k0 + 1)] = f2tf32(v.y);
        row[permk(k0 + 2)] = f2tf32(v.z);
        row[permk(k0 + 3)] = f2tf32(v.w);
    }

    float acc[4][8][4];
#pragma unroll
    for (int mt = 0; mt < 4; mt++)
#pragma unroll
        for (int nt = 0; nt < 8; nt++)
#pragma unroll
            for (int i = 0; i < 4; i++) acc[mt][nt][i] = 0.f;

    __syncthreads();   // Bs ready (also covers first A sync below with wait_group)

    for (int kt = 0; kt < KSTEPS; kt++) {
        const int buf = kt & 1;
        asm volatile("cp.async.wait_group 1;");
        __syncthreads();

        const float* Abuf = &As[(size_t)buf * BM * AS_STRIDE];
        const int kb = kt * BK;

#pragma unroll
        for (int ks = 0; ks < BK; ks += 8) {
            uint32_t a[4][4];
#pragma unroll
            for (int mt = 0; mt < 4; mt++) {
                const float* ar = Abuf + (wm + mt * 16 + g) * AS_STRIDE + ks + t;
                a[mt][0] = f2tf32(ar[0]);
                a[mt][1] = f2tf32(ar[8 * AS_STRIDE]);
                a[mt][2] = f2tf32(ar[4]);
                a[mt][3] = f2tf32(ar[8 * AS_STRIDE + 4]);
            }
            uint32_t b[8][2];
#pragma unroll
            for (int nt = 0; nt < 8; nt++) {
                const uint2 bv = *(const uint2*)&Bs[(wn + nt * 8 + g) * BS_STRIDE + kb + ks + 2 * t];
                b[nt][0] = bv.x;
                b[nt][1] = bv.y;
            }
#pragma unroll
            for (int mt = 0; mt < 4; mt++)
#pragma unroll
                for (int nt = 0; nt < 8; nt++)
                    mma_tf32(acc[mt][nt], a[mt], b[nt]);
        }

        __syncthreads();
        if (kt + 2 < KSTEPS) issueA(kt + 2, buf);
        asm volatile("cp.async.commit_group;");
    }

    // ---- epilogue ----
    const bool has_bias = (bias != nullptr);
#pragma unroll
    for (int mt = 0; mt < 4; mt++) {
        const int r0 = wm + mt * 16 + g;
#pragma unroll
        for (int nt = 0; nt < 8; nt++) {
            const int c = wn + nt * 8 + 2 * t;
            float v0 = acc[mt][nt][0], v1 = acc[mt][nt][1];
            float v2 = acc[mt][nt][2], v3 = acc[mt][nt][3];
            if (has_bias) {
                v0 += s_bias[c]; v1 += s_bias[c + 1];
                v2 += s_bias[c]; v3 += s_bias[c + 1];
            }
            if (relu) {
                v0 = fmaxf(v0, 0.f); v1 = fmaxf(v1, 0.f);
                v2 = fmaxf(v2, 0.f); v3 = fmaxf(v3, 0.f);
            }
            *(float2*)&Cb[(size_t)r0 * 256 + c]       = make_float2(v0, v1);
            *(float2*)&Cb[(size_t)(r0 + 8) * 256 + c] = make_float2(v2, v3);
        }
    }
}

// ---------------------------------------------------------------------------
// Launch. Inputs: queries, feature_values, feature_indices, query_batch_offsets,
// W1,b1,W2,b2,W3,b3,W4,b4. Indices/offsets don't affect output values.
// ---------------------------------------------------------------------------
extern "C" void kernel_launch(void* const* d_in, const int* in_sizes, int n_in,
                              void* d_out, int out_size)
{
    (void)in_sizes; (void)n_in; (void)out_size;
    const float* queries = (const float*)d_in[0];
    const float* feats   = (const float*)d_in[1];
    const float* W1 = (const float*)d_in[4];
    const float* b1 = (const float*)d_in[5];
    const float* W2 = (const float*)d_in[6];
    const float* b2 = (const float*)d_in[7];
    const float* W3 = (const float*)d_in[8];
    const float* b3 = (const float*)d_in[9];
    const float* W4 = (const float*)d_in[10];
    const float* b4 = (const float*)d_in[11];
    float* out = (float*)d_out;

    float *p1 = nullptr, *p2 = nullptr;
    cudaGetSymbolAddress((void**)&p1, g_buf1);
    cudaGetSymbolAddress((void**)&p2, g_buf2);

    static bool attr_set = false;
    if (!attr_set) {
        cudaFuncSetAttribute(gemm_mma, cudaFuncAttributeMaxDynamicSharedMemorySize, DYN_SMEM);
        attr_set = true;
    }

    // MLP: M=1024 -> grid (2, 4); B = W (torch [out,in], K-major)
    dim3 mg(2, NQ_ / BM, 1);
    gemm_mma<<<mg, 256, DYN_SMEM>>>(queries, W1, p1, b1, 1, 0, 0, 0);
    gemm_mma<<<mg, 256, DYN_SMEM>>>(p1,      W2, p2, b2, 1, 0, 0, 0);
    gemm_mma<<<mg, 256, DYN_SMEM>>>(p2,      W3, p1, b3, 1, 0, 0, 0);
    gemm_mma<<<mg, 256, DYN_SMEM>>>(p1,      W4, p2, b4, 0, 0, 0, 0);

    // Logits: per batch A = feats[b] (65536 x 256), B = mlp-out[b] (256 x 256)
    gemm_mma<<<dim3(2, NF_ / BM, B_), 256, DYN_SMEM>>>(
        feats, p2, out, nullptr, 0,
        (long long)NF_ * KDIM, (long long)256 * KDIM, (long long)NF_ * 256);
}

// round 5
// speedup vs baseline: 1.2827x; 1.2827x over previous
#include <cuda_runtime.h>
#include <cuda_fp16.h>
#include <cstdint>
#include <cstddef>

#define KDIM 256
#define NQ_  1024
#define B_   4
#define NF_  65536

// scratch (__device__ globals: the sanctioned no-alloc path)
__device__ float  g_buf1[NQ_ * KDIM];
__device__ float  g_buf2[NQ_ * KDIM];
__device__ __half g_wh[4 * KDIM * KDIM];   // fp16 weights, [layer][out][in]
__device__ __half g_qh[NQ_ * KDIM];        // fp16 MLP output (logits B operand)

// ---------------------------------------------------------------------------
// prep: convert the 4 weight matrices f32 -> fp16 (once per launch, ~2us)
// ---------------------------------------------------------------------------
__global__ void prep_w(const float* __restrict__ W1, const float* __restrict__ W2,
                       const float* __restrict__ W3, const float* __restrict__ W4)
{
    int idx = blockIdx.x * 256 + threadIdx.x;          // 65536 float4 total
    const float* src = (idx < 16384) ? W1 : (idx < 32768) ? W2 : (idx < 49152) ? W3 : W4;
    int off = idx & 16383;
    float4 v = ((const float4*)src)[off];
    __half2 h0 = __floats2half2_rn(v.x, v.y);
    __half2 h1 = __floats2half2_rn(v.z, v.w);
    uint2 u;
    u.x = *(uint32_t*)&h0;
    u.y = *(uint32_t*)&h1;
    ((uint2*)g_wh)[idx] = u;
}

// ---------------------------------------------------------------------------
// fp16 mma.sync GEMM: C[128 x 128] per CTA = A[128 x 256]_f32 @ B[128 x 256]_f16^T
//  - A: LDG float4 register prefetch -> cvt f16x2 -> STS.64 (swizzled smem)
//  - B: pre-converted fp16 global -> cp.async 16B (swizzled smem)
//  - fragments via ldmatrix.x4 (conflict-free: 128B smem rows pack (r, r+64),
//    16B-chunk index XOR (r&7))
//  - 8 warps 4(m) x 2(n), warp tile 32x64; mma m16n8k16 f16 -> f32 acc
// ---------------------------------------------------------------------------
__device__ __forceinline__ uint32_t cvta_s(const void* p) {
    return (uint32_t)__cvta_generic_to_shared(p);
}

#define LDM4(r0, r1, r2, r3, addr) \
    asm volatile("ldmatrix.sync.aligned.m8n8.x4.shared.b16 {%0,%1,%2,%3}, [%4];" \
                 : "=r"(r0), "=r"(r1), "=r"(r2), "=r"(r3) : "r"(addr))

#define MMA16(c, a, b0, b1) \
    asm volatile("mma.sync.aligned.m16n8k16.row.col.f32.f16.f16.f32 " \
                 "{%0,%1,%2,%3},{%4,%5,%6,%7},{%8,%9},{%0,%1,%2,%3};" \
                 : "+f"((c)[0]), "+f"((c)[1]), "+f"((c)[2]), "+f"((c)[3]) \
                 : "r"((a)[0]), "r"((a)[1]), "r"((a)[2]), "r"((a)[3]), "r"(b0), "r"(b1))

__global__ __launch_bounds__(256)
void gemm_f16(const float* __restrict__ A, const __half* __restrict__ Bh,
              float* __restrict__ C, __half* __restrict__ C16,
              const float* __restrict__ bias, int relu,
              long long aStride, long long bStride, long long cStride)
{
    __shared__ __align__(128) char As_[2][8192];   // 128 rows x 32 k fp16, packed+swizzled
    __shared__ __align__(128) char Bs_[2][8192];
    __shared__ float s_bias[128];

    const int tid = threadIdx.x;
    const int w = tid >> 5, l = tid & 31;
    const int g = l >> 2, t = l & 3;
    const int wm = (w & 3) * 32;    // warp m origin
    const int wn = (w >> 2) * 64;   // warp n origin

    const int nb = blockIdx.x;      // n-inner: the 2 n-blocks share the A tile via L2
    const int mb = blockIdx.y;
    const long long bb = blockIdx.z;

    const float* Ab = A + bb * aStride + (size_t)mb * 128 * KDIM;
    const __half* Bb = Bh + bb * bStride + (size_t)nb * 128 * KDIM;

    if (bias && tid < 128) s_bias[tid] = bias[nb * 128 + tid];

    // smem byte for (row r, 16B-chunk c within the row's 64B):
    //   (r&63)*128 + ((((r>>6)*4 + c) ^ (r&7)) * 16
    // ldmatrix A source addrs (buf0, k16-group 0)
    uint32_t a_addr[2];
    {
        int r = wm + (l & 7) + ((l >> 3) & 1) * 8;
        int ck = (l >> 4) & 1;
#pragma unroll
        for (int mt = 0; mt < 2; mt++) {
            int rr = r + mt * 16;
            int cp = (((rr >> 6) * 4 + ck) ^ (rr & 7));
            a_addr[mt] = cvta_s(&As_[0][(rr & 63) * 128 + cp * 16]);
        }
    }
    // ldmatrix B source addrs
    uint32_t b_addr[4];
    {
        int n = wn + (l & 7) + ((l >> 4) & 1) * 8;
        int ck = (l >> 3) & 1;
#pragma unroll
        for (int p = 0; p < 4; p++) {
            int nn = n + p * 16;
            int cp = (((nn >> 6) * 4 + ck) ^ (nn & 7));
            b_addr[p] = cvta_s(&Bs_[0][(nn & 63) * 128 + cp * 16]);
        }
    }

    // A store addrs: thread handles rows r_i = i*32 + (tid>>3), float-group f = tid&7
    const int fA = tid & 7;
    uint32_t sts_addr[4];
#pragma unroll
    for (int i = 0; i < 4; i++) {
        int r = i * 32 + (tid >> 3);
        int cp = (((r >> 6) * 4 + (fA >> 1)) ^ (r & 7));
        sts_addr[i] = cvta_s(&As_[0][(r & 63) * 128 + cp * 16 + (fA & 1) * 8]);
    }
    const float* aload = Ab + (size_t)(tid >> 3) * KDIM + fA * 4;

    // B cp.async: 2 chunks per thread
    uint32_t bst_addr[2];
    const __half* bld[2];
#pragma unroll
    for (int i = 0; i < 2; i++) {
        int cid = tid * 2 + i;
        int n = cid >> 2, c = cid & 3;
        int cp = (((n >> 6) * 4 + c) ^ (n & 7));
        bst_addr[i] = cvta_s(&Bs_[0][(n & 63) * 128 + cp * 16]);
        bld[i] = Bb + (size_t)n * KDIM + c * 8;
    }

    // preload k-chunk 0
    float4 pre[4];
#pragma unroll
    for (int i = 0; i < 4; i++) pre[i] = *(const float4*)(aload + (size_t)i * 32 * KDIM);
#pragma unroll
    for (int i = 0; i < 2; i++)
        asm volatile("cp.async.cg.shared.global [%0], [%1], 16;"
                     :: "r"(bst_addr[i]), "l"(bld[i]));
    asm volatile("cp.async.commit_group;");

    float acc[2][8][4];
#pragma unroll
    for (int mt = 0; mt < 2; mt++)
#pragma unroll
        for (int nt = 0; nt < 8; nt++)
#pragma unroll
            for (int i = 0; i < 4; i++) acc[mt][nt][i] = 0.f;

    for (int kt = 0; kt < 8; kt++) {
        const uint32_t buf = (kt & 1) * 8192;

        // store A(kt) fp16 into smem
#pragma unroll
        for (int i = 0; i < 4; i++) {
            __half2 h0 = __floats2half2_rn(pre[i].x, pre[i].y);
            __half2 h1 = __floats2half2_rn(pre[i].z, pre[i].w);
            asm volatile("st.shared.v2.b32 [%0], {%1,%2};"
                         :: "r"(sts_addr[i] + buf), "r"(*(uint32_t*)&h0), "r"(*(uint32_t*)&h1));
        }
        // prefetch A(kt+1) into registers
        if (kt < 7) {
#pragma unroll
            for (int i = 0; i < 4; i++)
                pre[i] = *(const float4*)(aload + (size_t)i * 32 * KDIM + (kt + 1) * 32);
        }
        asm volatile("cp.async.wait_group 0;");
        __syncthreads();
        // issue B(kt+1)
        if (kt < 7) {
            const uint32_t nbuf = ((kt + 1) & 1) * 8192;
#pragma unroll
            for (int i = 0; i < 2; i++)
                asm volatile("cp.async.cg.shared.global [%0], [%1], 16;"
                             :: "r"(bst_addr[i] + nbuf), "l"(bld[i] + (kt + 1) * 32));
            asm volatile("cp.async.commit_group;");
        }

        // MMA on chunk kt (2 x k16)
#pragma unroll
        for (int g16 = 0; g16 < 2; g16++) {
            const uint32_t xo = g16 * 32;
            uint32_t a0[4], a1[4];
            LDM4(a0[0], a0[1], a0[2], a0[3], (a_addr[0] + buf) ^ xo);
            LDM4(a1[0], a1[1], a1[2], a1[3], (a_addr[1] + buf) ^ xo);
            uint32_t bf[4][4];
#pragma unroll
            for (int p = 0; p < 4; p++)
                LDM4(bf[p][0], bf[p][1], bf[p][2], bf[p][3], (b_addr[p] + buf) ^ xo);
#pragma unroll
            for (int nt = 0; nt < 8; nt++) {
                uint32_t b0 = bf[nt >> 1][(nt & 1) * 2];
                uint32_t b1 = bf[nt >> 1][(nt & 1) * 2 + 1];
                MMA16(acc[0][nt], a0, b0, b1);
                MMA16(acc[1][nt], a1, b0, b1);
            }
        }
    }

    // ---------------- epilogue ----------------
    const bool hb = (bias != nullptr);
    const long long cbase = bb * cStride;
#pragma unroll
    for (int mt = 0; mt < 2; mt++) {
        const int r0 = mb * 128 + wm + mt * 16 + g;
#pragma unroll
        for (int nt = 0; nt < 8; nt++) {
            const int cl = wn + nt * 8 + 2 * t;          // local col 0..127
            const int c = nb * 128 + cl;                  // global col 0..255
            float v0 = acc[mt][nt][0], v1 = acc[mt][nt][1];
            float v2 = acc[mt][nt][2], v3 = acc[mt][nt][3];
            if (hb) {
                float bi0 = s_bias[cl], bi1 = s_bias[cl + 1];
                v0 += bi0; v1 += bi1; v2 += bi0; v3 += bi1;
            }
            if (relu) {
                v0 = fmaxf(v0, 0.f); v1 = fmaxf(v1, 0.f);
                v2 = fmaxf(v2, 0.f); v3 = fmaxf(v3, 0.f);
            }
            if (C16) {
                *(__half2*)&C16[(size_t)r0 * 256 + c]       = __floats2half2_rn(v0, v1);
                *(__half2*)&C16[(size_t)(r0 + 8) * 256 + c] = __floats2half2_rn(v2, v3);
            } else {
                *(float2*)&C[cbase + (size_t)r0 * 256 + c]       = make_float2(v0, v1);
                *(float2*)&C[cbase + (size_t)(r0 + 8) * 256 + c] = make_float2(v2, v3);
            }
        }
    }
}

// ---------------------------------------------------------------------------
// Launch. Inputs: queries, feature_values, feature_indices, query_batch_offsets,
// W1,b1,W2,b2,W3,b3,W4,b4. Indices/offsets don't affect output values.
// ---------------------------------------------------------------------------
extern "C" void kernel_launch(void* const* d_in, const int* in_sizes, int n_in,
                              void* d_out, int out_size)
{
    (void)in_sizes; (void)n_in; (void)out_size;
    const float* queries = (const float*)d_in[0];
    const float* feats   = (const float*)d_in[1];
    const float* W1 = (const float*)d_in[4];
    const float* b1 = (const float*)d_in[5];
    const float* W2 = (const float*)d_in[6];
    const float* b2 = (const float*)d_in[7];
    const float* W3 = (const float*)d_in[8];
    const float* b3 = (const float*)d_in[9];
    const float* W4 = (const float*)d_in[10];
    const float* b4 = (const float*)d_in[11];
    float* out = (float*)d_out;

    float *p1 = nullptr, *p2 = nullptr;
    __half *wh = nullptr, *qh = nullptr;
    cudaGetSymbolAddress((void**)&p1, g_buf1);
    cudaGetSymbolAddress((void**)&p2, g_buf2);
    cudaGetSymbolAddress((void**)&wh, g_wh);
    cudaGetSymbolAddress((void**)&qh, g_qh);

    prep_w<<<256, 256>>>(W1, W2, W3, W4);

    // MLP: M=1024 (grid 2x8), K=256; layer 4 writes fp16 directly (logits B operand)
    dim3 mg(2, 8, 1);
    gemm_f16<<<mg, 256>>>(queries, wh,               p1, nullptr, b1, 1, 0, 0, 0);
    gemm_f16<<<mg, 256>>>(p1,      wh + 1 * 65536,   p2, nullptr, b2, 1, 0, 0, 0);
    gemm_f16<<<mg, 256>>>(p2,      wh + 2 * 65536,   p1, nullptr, b3, 1, 0, 0, 0);
    gemm_f16<<<mg, 256>>>(p1,      wh + 3 * 65536,   p2, qh,      b4, 0, 0, 0, 0);

    // Logits: per batch A = feats[b] (65536 x 256) f32, B = qh[b] (256 x 256) fp16
    gemm_f16<<<dim3(2, NF_ / 128, B_), 256>>>(
        feats, qh, out, nullptr, nullptr, 0,
        (long long)NF_ * KDIM, (long long)256 * KDIM, (long long)NF_ * 256);
}

// round 6
// speedup vs baseline: 1.9702x; 1.5359x over previous
#include <cuda_runtime.h>
#include <cuda_fp16.h>
#include <cstdint>
#include <cstddef>

#define KDIM 256
#define NQ_  1024
#define B_   4
#define NF_  65536

// scratch (__device__ globals: the sanctioned no-alloc path)
__device__ __half g_wh[4 * KDIM * KDIM];   // fp16 weights, [layer][out][in]
__device__ __half g_qh[NQ_ * KDIM];        // fp16 MLP output (logits B operand)

__device__ __forceinline__ uint32_t cvta_s(const void* p) {
    return (uint32_t)__cvta_generic_to_shared(p);
}

#define LDM4(r0, r1, r2, r3, addr) \
    asm volatile("ldmatrix.sync.aligned.m8n8.x4.shared.b16 {%0,%1,%2,%3}, [%4];" \
                 : "=r"(r0), "=r"(r1), "=r"(r2), "=r"(r3) : "r"(addr))

#define MMA16(c, a, b0, b1) \
    asm volatile("mma.sync.aligned.m16n8k16.row.col.f32.f16.f16.f32 " \
                 "{%0,%1,%2,%3},{%4,%5,%6,%7},{%8,%9},{%0,%1,%2,%3};" \
                 : "+f"((c)[0]), "+f"((c)[1]), "+f"((c)[2]), "+f"((c)[3]) \
                 : "r"((a)[0]), "r"((a)[1]), "r"((a)[2]), "r"((a)[3]), "r"(b0), "r"(b1))

#define CP16(dst, src) \
    asm volatile("cp.async.cg.shared.global [%0], [%1], 16;" :: "r"(dst), "l"(src))

// ---------------------------------------------------------------------------
// prep: convert the 4 weight matrices f32 -> fp16 (once per launch)
// ---------------------------------------------------------------------------
__global__ void prep_w(const float* __restrict__ W1, const float* __restrict__ W2,
                       const float* __restrict__ W3, const float* __restrict__ W4)
{
    int idx = blockIdx.x * 256 + threadIdx.x;          // 65536 float4 total
    const float* src = (idx < 16384) ? W1 : (idx < 32768) ? W2 : (idx < 49152) ? W3 : W4;
    int off = idx & 16383;
    float4 v = ((const float4*)src)[off];
    __half2 h0 = __floats2half2_rn(v.x, v.y);
    __half2 h1 = __floats2half2_rn(v.z, v.w);
    uint2 u;
    u.x = *(uint32_t*)&h0;
    u.y = *(uint32_t*)&h1;
    ((uint2*)g_wh)[idx] = u;
}

// ---------------------------------------------------------------------------
// Fused 4-layer MLP. Grid = 16 CTAs, each pushes 64 query rows through all
// 4 layers. x ping-pongs in SMEM (fp16, swizzled); W streamed via 3-stage
// cp.async ring from L2; final layer writes fp16 qh.
// x layout (64 rows, chunked by 32 halfs):
//   addr = chunk*4096 + (r&31)*128 + ((((r>>5)*4)+c16)^(r&7))*16   (c16=0..3)
// W layout (256 rows per chunk):
//   addr = (n&127)*128 + ((((n>>7)*4)+c)^(n&7))*16
// ---------------------------------------------------------------------------
#define MLP_SMEM (65536 + 49152 + 4096)   // x(2x32KB) + Wring(3x16KB) + bias

__global__ __launch_bounds__(256) void mlp_fused(
    const float* __restrict__ Q, const __half* __restrict__ wh,
    const float* __restrict__ b1, const float* __restrict__ b2,
    const float* __restrict__ b3, const float* __restrict__ b4,
    __half* __restrict__ qh)
{
    extern __shared__ char sm[];
    char*  xb = sm;                        // 2 x 32768
    char*  ws = sm + 65536;                // 3 x 16384
    float* sb = (float*)(sm + 65536 + 49152);

    const int tid = threadIdx.x;
    const int w = tid >> 5, l = tid & 31;
    const int g = l >> 2, t = l & 3;
    const int wm = (w & 1) * 32;     // 2 m-warps
    const int wn = (w >> 1) * 64;    // 4 n-warps
    const int m0 = blockIdx.x * 64;

    {   // biases: sb[L*256 + n]
        const float* bs0 = b1; const float* bs1 = b2;
        const float* bs2 = b3; const float* bs3 = b4;
        sb[tid] = bs0[tid]; sb[256 + tid] = bs1[tid];
        sb[512 + tid] = bs2[tid]; sb[768 + tid] = bs3[tid];
    }

    // queries f32 -> fp16 swizzled into xb[0]
#pragma unroll
    for (int i = 0; i < 16; i++) {
        int idx = tid + i * 256;
        int r = idx >> 6, k = (idx & 63) * 4;
        float4 v = *(const float4*)&Q[(size_t)(m0 + r) * KDIM + k];
        __half2 h0 = __floats2half2_rn(v.x, v.y);
        __half2 h1 = __floats2half2_rn(v.z, v.w);
        int chunk = k >> 5, c16 = (k & 31) >> 3, hi = (k >> 2) & 1;
        uint32_t ad = cvta_s(xb + chunk * 4096 + (r & 31) * 128
                             + ((((r >> 5) * 4) + c16) ^ (r & 7)) * 16 + hi * 8);
        asm volatile("st.shared.v2.b32 [%0], {%1,%2};"
                     :: "r"(ad), "r"(*(uint32_t*)&h0), "r"(*(uint32_t*)&h1));
    }

    // ldmatrix B (W) addrs (stage 0 base)
    uint32_t b_addr[4];
    {
        int n = wn + (l & 7) + ((l >> 4) & 1) * 8;
        int ck = (l >> 3) & 1;
#pragma unroll
        for (int p = 0; p < 4; p++) {
            int nn = n + p * 16;
            int cp = (((nn >> 7) * 4 + ck) ^ (nn & 7));
            b_addr[p] = cvta_s(ws + (nn & 127) * 128 + cp * 16);
        }
    }
    // W cp.async dsts: thread = row n, 4 x 16B chunks
    uint32_t wst[4];
#pragma unroll
    for (int c = 0; c < 4; c++)
        wst[c] = cvta_s(ws + (tid & 127) * 128 + ((((tid >> 7) * 4) + c) ^ (tid & 7)) * 16
                        + (tid >> 7) * 0);   // tid<256: (n&127), (n>>7) in formula below
    // note: tid up to 255 -> n>>7 is 0 or 1; fold correctly:
#pragma unroll
    for (int c = 0; c < 4; c++) {
        int n = tid;
        wst[c] = cvta_s(ws + (n & 127) * 128 + ((((n >> 7) * 4) + c) ^ (n & 7)) * 16);
    }

    __syncthreads();

    for (int L = 0; L < 4; L++) {
        const __half* Wl = wh + (size_t)L * 65536;
        const uint32_t xbase = (uint32_t)(L & 1) * 32768;

        uint32_t a_addr[2];
        {
            int r = wm + (l & 7) + ((l >> 3) & 1) * 8;
            int ck = (l >> 4) & 1;
#pragma unroll
            for (int mt = 0; mt < 2; mt++) {
                int rr = r + mt * 16;
                int cp = (((rr >> 5) * 4 + ck) ^ (rr & 7));
                a_addr[mt] = cvta_s(xb + xbase + (rr & 31) * 128 + cp * 16);
            }
        }

        // prologue: W chunks 0,1
#pragma unroll
        for (int s = 0; s < 2; s++) {
#pragma unroll
            for (int c = 0; c < 4; c++)
                CP16(wst[c] + s * 16384, Wl + (size_t)tid * KDIM + s * 32 + c * 8);
            asm volatile("cp.async.commit_group;");
        }

        float acc[2][8][4];
#pragma unroll
        for (int mt = 0; mt < 2; mt++)
#pragma unroll
            for (int nt = 0; nt < 8; nt++)
#pragma unroll
                for (int i = 0; i < 4; i++) acc[mt][nt][i] = 0.f;

#pragma unroll
        for (int kt = 0; kt < 8; kt++) {
            asm volatile("cp.async.wait_group 1;");
            __syncthreads();
            if (kt < 6) {
                int s = (kt + 2) % 3;
#pragma unroll
                for (int c = 0; c < 4; c++)
                    CP16(wst[c] + s * 16384, Wl + (size_t)tid * KDIM + (kt + 2) * 32 + c * 8);
            }
            asm volatile("cp.async.commit_group;");

            const uint32_t abuf = kt * 4096;
            const uint32_t bbuf = (kt % 3) * 16384;
#pragma unroll
            for (int g16 = 0; g16 < 2; g16++) {
                const uint32_t xo = g16 * 32;
                uint32_t a0[4], a1[4];
                LDM4(a0[0], a0[1], a0[2], a0[3], (a_addr[0] + abuf) ^ xo);
                LDM4(a1[0], a1[1], a1[2], a1[3], (a_addr[1] + abuf) ^ xo);
                uint32_t bf[4][4];
#pragma unroll
                for (int p = 0; p < 4; p++)
                    LDM4(bf[p][0], bf[p][1], bf[p][2], bf[p][3], (b_addr[p] + bbuf) ^ xo);
#pragma unroll
                for (int nt = 0; nt < 8; nt++) {
                    uint32_t q0 = bf[nt >> 1][(nt & 1) * 2];
                    uint32_t q1 = bf[nt >> 1][(nt & 1) * 2 + 1];
                    MMA16(acc[0][nt], a0, q0, q1);
                    MMA16(acc[1][nt], a1, q0, q1);
                }
            }
        }

        __syncthreads();   // all reads done before overwriting pong / W ring

        if (L < 3) {
            const uint32_t pong = (uint32_t)((L & 1) ^ 1) * 32768;
#pragma unroll
            for (int mt = 0; mt < 2; mt++) {
#pragma unroll
                for (int nt = 0; nt < 8; nt++) {
                    int r = wm + mt * 16 + g;
                    int c = wn + nt * 8 + 2 * t;
                    float bi0 = sb[L * 256 + c], bi1 = sb[L * 256 + c + 1];
                    float v0 = fmaxf(acc[mt][nt][0] + bi0, 0.f);
                    float v1 = fmaxf(acc[mt][nt][1] + bi1, 0.f);
                    float v2 = fmaxf(acc[mt][nt][2] + bi0, 0.f);
                    float v3 = fmaxf(acc[mt][nt][3] + bi1, 0.f);
                    __half2 h01 = __floats2half2_rn(v0, v1);
                    __half2 h23 = __floats2half2_rn(v2, v3);
                    int chunk = c >> 5, c16 = (c & 31) >> 3, bo = (c & 7) * 2;
                    int r8 = r + 8;
                    uint32_t ad0 = cvta_s(xb + pong + chunk * 4096 + (r & 31) * 128
                                   + ((((r >> 5) * 4) + c16) ^ (r & 7)) * 16 + bo);
                    uint32_t ad1 = cvta_s(xb + pong + chunk * 4096 + (r8 & 31) * 128
                                   + ((((r8 >> 5) * 4) + c16) ^ (r8 & 7)) * 16 + bo);
                    asm volatile("st.shared.b32 [%0], %1;" :: "r"(ad0), "r"(*(uint32_t*)&h01));
                    asm volatile("st.shared.b32 [%0], %1;" :: "r"(ad1), "r"(*(uint32_t*)&h23));
                }
            }
        } else {
#pragma unroll
            for (int mt = 0; mt < 2; mt++) {
#pragma unroll
                for (int nt = 0; nt < 8; nt++) {
                    int r = m0 + wm + mt * 16 + g;
                    int c = wn + nt * 8 + 2 * t;
                    float bi0 = sb[768 + c], bi1 = sb[768 + c + 1];
                    __half2 h01 = __floats2half2_rn(acc[mt][nt][0] + bi0, acc[mt][nt][1] + bi1);
                    __half2 h23 = __floats2half2_rn(acc[mt][nt][2] + bi0, acc[mt][nt][3] + bi1);
                    *(__half2*)&qh[(size_t)r * KDIM + c]       = h01;
                    *(__half2*)&qh[(size_t)(r + 8) * KDIM + c] = h23;
                }
            }
        }
        __syncthreads();
    }
}

// ---------------------------------------------------------------------------
// Logits GEMM: C[128 x 128] per CTA = feats[128 x 256]_f32 @ qh[128 x 256]_f16^T
//  - A: LDG float4 prefetch TWO chunks ahead -> cvt -> STS (swizzled)
//  - B: 4-stage cp.async ring, wait_group 2
//  - 8 warps 4(m) x 2(n), warp tile 32x64, ldmatrix.x4 fragments
// ---------------------------------------------------------------------------
#define LOG_SMEM (2 * 8192 + 4 * 8192)   // 49152

__global__ __launch_bounds__(256)
void gemm_logits(const float* __restrict__ A, const __half* __restrict__ Bh,
                 float* __restrict__ C)
{
    extern __shared__ char sm[];
    char* As_ = sm;            // 2 x 8192
    char* Bs_ = sm + 16384;    // 4 x 8192

    const int tid = threadIdx.x;
    const int w = tid >> 5, l = tid & 31;
    const int g = l >> 2, t = l & 3;
    const int wm = (w & 3) * 32;
    const int wn = (w >> 2) * 64;

    const int nb = blockIdx.x;   // n-inner: nb pair shares the A tile via L2
    const int mb = blockIdx.y;
    const long long bb = blockIdx.z;

    const float* Ab = A + bb * ((long long)NF_ * KDIM) + (size_t)mb * 128 * KDIM;
    const __half* Bb = Bh + bb * ((long long)256 * KDIM) + (size_t)nb * 128 * KDIM;
    float* Cb = C + bb * ((long long)NF_ * 256) + (size_t)mb * 128 * 256 + (size_t)nb * 128;

    // ldmatrix A addrs (buf0)
    uint32_t a_addr[2];
    {
        int r = wm + (l & 7) + ((l >> 3) & 1) * 8;
        int ck = (l >> 4) & 1;
#pragma unroll
        for (int mt = 0; mt < 2; mt++) {
            int rr = r + mt * 16;
            int cp = (((rr >> 6) * 4 + ck) ^ (rr & 7));
            a_addr[mt] = cvta_s(As_ + (rr & 63) * 128 + cp * 16);
        }
    }
    // ldmatrix B addrs (stage0)
    uint32_t b_addr[4];
    {
        int n = wn + (l & 7) + ((l >> 4) & 1) * 8;
        int ck = (l >> 3) & 1;
#pragma unroll
        for (int p = 0; p < 4; p++) {
            int nn = n + p * 16;
            int cp = (((nn >> 6) * 4 + ck) ^ (nn & 7));
            b_addr[p] = cvta_s(Bs_ + (nn & 63) * 128 + cp * 16);
        }
    }
    // A STS addrs (buf0): thread -> rows i*32+(tid>>3), float-group fA
    const int fA = tid & 7;
    uint32_t sts_addr[4];
    const float* aload[4];
#pragma unroll
    for (int i = 0; i < 4; i++) {
        int r = i * 32 + (tid >> 3);
        int cp = (((r >> 6) * 4 + (fA >> 1)) ^ (r & 7));
        sts_addr[i] = cvta_s(As_ + (r & 63) * 128 + cp * 16 + (fA & 1) * 8);
        aload[i] = Ab + (size_t)r * KDIM + fA * 4;
    }
    // B cp.async: 2 chunks/thread (stage0 dsts)
    uint32_t bst_addr[2];
    const __half* bld[2];
#pragma unroll
    for (int i = 0; i < 2; i++) {
        int cid = tid * 2 + i;
        int n = cid >> 2, c = cid & 3;
        int cp = (((n >> 6) * 4 + c) ^ (n & 7));
        bst_addr[i] = cvta_s(Bs_ + (n & 63) * 128 + cp * 16);
        bld[i] = Bb + (size_t)n * KDIM + c * 8;
    }

    // prologue: A chunks 0,1 into regs; B stages 0,1,2
    float4 pre[2][4];
#pragma unroll
    for (int i = 0; i < 4; i++) {
        pre[0][i] = *(const float4*)(aload[i]);
        pre[1][i] = *(const float4*)(aload[i] + 32);
    }
#pragma unroll
    for (int s = 0; s < 3; s++) {
#pragma unroll
        for (int i = 0; i < 2; i++)
            CP16(bst_addr[i] + s * 8192, bld[i] + s * 32);
        asm volatile("cp.async.commit_group;");
    }

    float acc[2][8][4];
#pragma unroll
    for (int mt = 0; mt < 2; mt++)
#pragma unroll
        for (int nt = 0; nt < 8; nt++)
#pragma unroll
            for (int i = 0; i < 4; i++) acc[mt][nt][i] = 0.f;

#pragma unroll
    for (int kt = 0; kt < 8; kt++) {
        const uint32_t abuf = (kt & 1) * 8192;

        // STS A(kt) from reg buffer, then prefetch A(kt+2) into same buffer
#pragma unroll
        for (int i = 0; i < 4; i++) {
            __half2 h0 = __floats2half2_rn(pre[kt & 1][i].x, pre[kt & 1][i].y);
            __half2 h1 = __floats2half2_rn(pre[kt & 1][i].z, pre[kt & 1][i].w);
            asm volatile("st.shared.v2.b32 [%0], {%1,%2};"
                         :: "r"(sts_addr[i] + abuf),
                            "r"(*(uint32_t*)&h0), "r"(*(uint32_t*)&h1));
        }
        if (kt < 6) {
#pragma unroll
            for (int i = 0; i < 4; i++)
                pre[kt & 1][i] = *(const float4*)(aload[i] + (kt + 2) * 32);
        }

        asm volatile("cp.async.wait_group 2;");   // B(kt) resident
        __syncthreads();

        if (kt < 5) {
            const uint32_t ns = ((kt + 3) & 3) * 8192;
#pragma unroll
            for (int i = 0; i < 2; i++)
                CP16(bst_addr[i] + ns, bld[i] + (kt + 3) * 32);
        }
        asm volatile("cp.async.commit_group;");   // always commit (uniform accounting)

        const uint32_t bbuf = (kt & 3) * 8192;
#pragma unroll
        for (int g16 = 0; g16 < 2; g16++) {
            const uint32_t xo = g16 * 32;
            uint32_t a0[4], a1[4];
            LDM4(a0[0], a0[1], a0[2], a0[3], (a_addr[0] + abuf) ^ xo);
            LDM4(a1[0], a1[1], a1[2], a1[3], (a_addr[1] + abuf) ^ xo);
            uint32_t bf[4][4];
#pragma unroll
            for (int p = 0; p < 4; p++)
                LDM4(bf[p][0], bf[p][1], bf[p][2], bf[p][3], (b_addr[p] + bbuf) ^ xo);
#pragma unroll
            for (int nt = 0; nt < 8; nt++) {
                uint32_t q0 = bf[nt >> 1][(nt & 1) * 2];
                uint32_t q1 = bf[nt >> 1][(nt & 1) * 2 + 1];
                MMA16(acc[0][nt], a0, q0, q1);
                MMA16(acc[1][nt], a1, q0, q1);
            }
        }
    }

    // epilogue: streaming stores (don't thrash L2)
#pragma unroll
    for (int mt = 0; mt < 2; mt++) {
        const int r0 = wm + mt * 16 + g;
#pragma unroll
        for (int nt = 0; nt < 8; nt++) {
            const int c = wn + nt * 8 + 2 * t;
            __stcs((float2*)&Cb[(size_t)r0 * 256 + c],
                   make_float2(acc[mt][nt][0], acc[mt][nt][1]));
            __stcs((float2*)&Cb[(size_t)(r0 + 8) * 256 + c],
                   make_float2(acc[mt][nt][2], acc[mt][nt][3]));
        }
    }
}

// ---------------------------------------------------------------------------
// Launch. Inputs: queries, feature_values, feature_indices, query_batch_offsets,
// W1,b1,W2,b2,W3,b3,W4,b4. Indices/offsets don't affect output values.
// ---------------------------------------------------------------------------
extern "C" void kernel_launch(void* const* d_in, const int* in_sizes, int n_in,
                              void* d_out, int out_size)
{
    (void)in_sizes; (void)n_in; (void)out_size;
    const float* queries = (const float*)d_in[0];
    const float* feats   = (const float*)d_in[1];
    const float* W1 = (const float*)d_in[4];
    const float* b1 = (const float*)d_in[5];
    const float* W2 = (const float*)d_in[6];
    const float* b2 = (const float*)d_in[7];
    const float* W3 = (const float*)d_in[8];
    const float* b3 = (const float*)d_in[9];
    const float* W4 = (const float*)d_in[10];
    const float* b4 = (const float*)d_in[11];
    float* out = (float*)d_out;

    __half *wh = nullptr, *qh = nullptr;
    cudaGetSymbolAddress((void**)&wh, g_wh);
    cudaGetSymbolAddress((void**)&qh, g_qh);

    cudaFuncSetAttribute(mlp_fused,   cudaFuncAttributeMaxDynamicSharedMemorySize, MLP_SMEM);
    cudaFuncSetAttribute(gemm_logits, cudaFuncAttributeMaxDynamicSharedMemorySize, LOG_SMEM);

    prep_w<<<256, 256>>>(W1, W2, W3, W4);
    mlp_fused<<<16, 256, MLP_SMEM>>>(queries, wh, b1, b2, b3, b4, qh);
    gemm_logits<<<dim3(2, NF_ / 128, B_), 256, LOG_SMEM>>>(feats, qh, out);
}

// round 7
// speedup vs baseline: 1.9885x; 1.0093x over previous
#include <cuda_runtime.h>
#include <cuda_fp16.h>
#include <cstdint>
#include <cstddef>

#define KDIM 256
#define NQ_  1024
#define B_   4
#define NF_  65536

// scratch (__device__ globals: the sanctioned no-alloc path)
__device__ __half g_wh[4 * KDIM * KDIM];   // fp16 weights, [layer][out][in]
__device__ __half g_qh[NQ_ * KDIM];        // fp16 MLP output (logits B operand)

__device__ __forceinline__ uint32_t cvta_s(const void* p) {
    return (uint32_t)__cvta_generic_to_shared(p);
}

#define LDM4(r0, r1, r2, r3, addr) \
    asm volatile("ldmatrix.sync.aligned.m8n8.x4.shared.b16 {%0,%1,%2,%3}, [%4];" \
                 : "=r"(r0), "=r"(r1), "=r"(r2), "=r"(r3) : "r"(addr))

#define MMA16(c, a, b0, b1) \
    asm volatile("mma.sync.aligned.m16n8k16.row.col.f32.f16.f16.f32 " \
                 "{%0,%1,%2,%3},{%4,%5,%6,%7},{%8,%9},{%0,%1,%2,%3};" \
                 : "+f"((c)[0]), "+f"((c)[1]), "+f"((c)[2]), "+f"((c)[3]) \
                 : "r"((a)[0]), "r"((a)[1]), "r"((a)[2]), "r"((a)[3]), "r"(b0), "r"(b1))

#define CP16(dst, src) \
    asm volatile("cp.async.cg.shared.global [%0], [%1], 16;" :: "r"(dst), "l"(src))

// ---------------------------------------------------------------------------
// prep: convert the 4 weight matrices f32 -> fp16 (once per launch)
// ---------------------------------------------------------------------------
__global__ void prep_w(const float* __restrict__ W1, const float* __restrict__ W2,
                       const float* __restrict__ W3, const float* __restrict__ W4)
{
    int idx = blockIdx.x * 256 + threadIdx.x;          // 65536 float4 total
    const float* src = (idx < 16384) ? W1 : (idx < 32768) ? W2 : (idx < 49152) ? W3 : W4;
    int off = idx & 16383;
    float4 v = ((const float4*)src)[off];
    __half2 h0 = __floats2half2_rn(v.x, v.y);
    __half2 h1 = __floats2half2_rn(v.z, v.w);
    uint2 u;
    u.x = *(uint32_t*)&h0;
    u.y = *(uint32_t*)&h1;
    ((uint2*)g_wh)[idx] = u;
}

// ---------------------------------------------------------------------------
// Fused 4-layer MLP (unchanged from round 6; ~10us)
// ---------------------------------------------------------------------------
#define MLP_SMEM (65536 + 49152 + 4096)

__global__ __launch_bounds__(256) void mlp_fused(
    const float* __restrict__ Q, const __half* __restrict__ wh,
    const float* __restrict__ b1, const float* __restrict__ b2,
    const float* __restrict__ b3, const float* __restrict__ b4,
    __half* __restrict__ qh)
{
    extern __shared__ char sm[];
    char*  xb = sm;                        // 2 x 32768
    char*  ws = sm + 65536;                // 3 x 16384
    float* sb = (float*)(sm + 65536 + 49152);

    const int tid = threadIdx.x;
    const int w = tid >> 5, l = tid & 31;
    const int g = l >> 2, t = l & 3;
    const int wm = (w & 1) * 32;
    const int wn = (w >> 1) * 64;
    const int m0 = blockIdx.x * 64;

    sb[tid] = b1[tid]; sb[256 + tid] = b2[tid];
    sb[512 + tid] = b3[tid]; sb[768 + tid] = b4[tid];

#pragma unroll
    for (int i = 0; i < 16; i++) {
        int idx = tid + i * 256;
        int r = idx >> 6, k = (idx & 63) * 4;
        float4 v = *(const float4*)&Q[(size_t)(m0 + r) * KDIM + k];
        __half2 h0 = __floats2half2_rn(v.x, v.y);
        __half2 h1 = __floats2half2_rn(v.z, v.w);
        int chunk = k >> 5, c16 = (k & 31) >> 3, hi = (k >> 2) & 1;
        uint32_t ad = cvta_s(xb + chunk * 4096 + (r & 31) * 128
                             + ((((r >> 5) * 4) + c16) ^ (r & 7)) * 16 + hi * 8);
        asm volatile("st.shared.v2.b32 [%0], {%1,%2};"
                     :: "r"(ad), "r"(*(uint32_t*)&h0), "r"(*(uint32_t*)&h1));
    }

    uint32_t b_addr[4];
    {
        int n = wn + (l & 7) + ((l >> 4) & 1) * 8;
        int ck = (l >> 3) & 1;
#pragma unroll
        for (int p = 0; p < 4; p++) {
            int nn = n + p * 16;
            int cp = (((nn >> 7) * 4 + ck) ^ (nn & 7));
            b_addr[p] = cvta_s(ws + (nn & 127) * 128 + cp * 16);
        }
    }
    uint32_t wst[4];
#pragma unroll
    for (int c = 0; c < 4; c++) {
        int n = tid;
        wst[c] = cvta_s(ws + (n & 127) * 128 + ((((n >> 7) * 4) + c) ^ (n & 7)) * 16);
    }

    __syncthreads();

    for (int L = 0; L < 4; L++) {
        const __half* Wl = wh + (size_t)L * 65536;
        const uint32_t xbase = (uint32_t)(L & 1) * 32768;

        uint32_t a_addr[2];
        {
            int r = wm + (l & 7) + ((l >> 3) & 1) * 8;
            int ck = (l >> 4) & 1;
#pragma unroll
            for (int mt = 0; mt < 2; mt++) {
                int rr = r + mt * 16;
                int cp = (((rr >> 5) * 4 + ck) ^ (rr & 7));
                a_addr[mt] = cvta_s(xb + xbase + (rr & 31) * 128 + cp * 16);
            }
        }

#pragma unroll
        for (int s = 0; s < 2; s++) {
#pragma unroll
            for (int c = 0; c < 4; c++)
                CP16(wst[c] + s * 16384, Wl + (size_t)tid * KDIM + s * 32 + c * 8);
            asm volatile("cp.async.commit_group;");
        }

        float acc[2][8][4];
#pragma unroll
        for (int mt = 0; mt < 2; mt++)
#pragma unroll
            for (int nt = 0; nt < 8; nt++)
#pragma unroll
                for (int i = 0; i < 4; i++) acc[mt][nt][i] = 0.f;

#pragma unroll
        for (int kt = 0; kt < 8; kt++) {
            asm volatile("cp.async.wait_group 1;");
            __syncthreads();
            if (kt < 6) {
                int s = (kt + 2) % 3;
#pragma unroll
                for (int c = 0; c < 4; c++)
                    CP16(wst[c] + s * 16384, Wl + (size_t)tid * KDIM + (kt + 2) * 32 + c * 8);
            }
            asm volatile("cp.async.commit_group;");

            const uint32_t abuf = kt * 4096;
            const uint32_t bbuf = (kt % 3) * 16384;
#pragma unroll
            for (int g16 = 0; g16 < 2; g16++) {
                const uint32_t xo = g16 * 32;
                uint32_t a0[4], a1[4];
                LDM4(a0[0], a0[1], a0[2], a0[3], (a_addr[0] + abuf) ^ xo);
                LDM4(a1[0], a1[1], a1[2], a1[3], (a_addr[1] + abuf) ^ xo);
                uint32_t bf[4][4];
#pragma unroll
                for (int p = 0; p < 4; p++)
                    LDM4(bf[p][0], bf[p][1], bf[p][2], bf[p][3], (b_addr[p] + bbuf) ^ xo);
#pragma unroll
                for (int nt = 0; nt < 8; nt++) {
                    uint32_t q0 = bf[nt >> 1][(nt & 1) * 2];
                    uint32_t q1 = bf[nt >> 1][(nt & 1) * 2 + 1];
                    MMA16(acc[0][nt], a0, q0, q1);
                    MMA16(acc[1][nt], a1, q0, q1);
                }
            }
        }

        __syncthreads();

        if (L < 3) {
            const uint32_t pong = (uint32_t)((L & 1) ^ 1) * 32768;
#pragma unroll
            for (int mt = 0; mt < 2; mt++) {
#pragma unroll
                for (int nt = 0; nt < 8; nt++) {
                    int r = wm + mt * 16 + g;
                    int c = wn + nt * 8 + 2 * t;
                    float bi0 = sb[L * 256 + c], bi1 = sb[L * 256 + c + 1];
                    float v0 = fmaxf(acc[mt][nt][0] + bi0, 0.f);
                    float v1 = fmaxf(acc[mt][nt][1] + bi1, 0.f);
                    float v2 = fmaxf(acc[mt][nt][2] + bi0, 0.f);
                    float v3 = fmaxf(acc[mt][nt][3] + bi1, 0.f);
                    __half2 h01 = __floats2half2_rn(v0, v1);
                    __half2 h23 = __floats2half2_rn(v2, v3);
                    int chunk = c >> 5, c16 = (c & 31) >> 3, bo = (c & 7) * 2;
                    int r8 = r + 8;
                    uint32_t ad0 = cvta_s(xb + pong + chunk * 4096 + (r & 31) * 128
                                   + ((((r >> 5) * 4) + c16) ^ (r & 7)) * 16 + bo);
                    uint32_t ad1 = cvta_s(xb + pong + chunk * 4096 + (r8 & 31) * 128
                                   + ((((r8 >> 5) * 4) + c16) ^ (r8 & 7)) * 16 + bo);
                    asm volatile("st.shared.b32 [%0], %1;" :: "r"(ad0), "r"(*(uint32_t*)&h01));
                    asm volatile("st.shared.b32 [%0], %1;" :: "r"(ad1), "r"(*(uint32_t*)&h23));
                }
            }
        } else {
#pragma unroll
            for (int mt = 0; mt < 2; mt++) {
#pragma unroll
                for (int nt = 0; nt < 8; nt++) {
                    int r = m0 + wm + mt * 16 + g;
                    int c = wn + nt * 8 + 2 * t;
                    float bi0 = sb[768 + c], bi1 = sb[768 + c + 1];
                    __half2 h01 = __floats2half2_rn(acc[mt][nt][0] + bi0, acc[mt][nt][1] + bi1);
                    __half2 h23 = __floats2half2_rn(acc[mt][nt][2] + bi0, acc[mt][nt][3] + bi1);
                    *(__half2*)&qh[(size_t)r * KDIM + c]       = h01;
                    *(__half2*)&qh[(size_t)(r + 8) * KDIM + c] = h23;
                }
            }
        }
        __syncthreads();
    }
}

// ---------------------------------------------------------------------------
// Logits GEMM, restaged: every stage opens compute-ready.
//  stage kt: ldmatrix(kt) | STS A(kt+1) | LDG A(kt+2) | cp.async B(kt+3)
//            | mma(kt) with wait_group between halves | sync at stage END
// ---------------------------------------------------------------------------
#define LOG_SMEM (2 * 8192 + 4 * 8192)   // 49152

__global__ __launch_bounds__(256)
void gemm_logits(const float* __restrict__ A, const __half* __restrict__ Bh,
                 float* __restrict__ C)
{
    extern __shared__ char sm[];
    char* As_ = sm;            // 2 x 8192
    char* Bs_ = sm + 16384;    // 4 x 8192

    const int tid = threadIdx.x;
    const int w = tid >> 5, l = tid & 31;
    const int g = l >> 2, t = l & 3;
    const int wm = (w & 3) * 32;
    const int wn = (w >> 2) * 64;

    const int nb = blockIdx.x;   // n-inner: nb pair shares the A tile via L2
    const int mb = blockIdx.y;
    const long long bb = blockIdx.z;

    const float* Ab = A + bb * ((long long)NF_ * KDIM) + (size_t)mb * 128 * KDIM;
    const __half* Bb = Bh + bb * ((long long)256 * KDIM) + (size_t)nb * 128 * KDIM;
    float* Cb = C + bb * ((long long)NF_ * 256) + (size_t)mb * 128 * 256 + (size_t)nb * 128;

    // ldmatrix A addrs (buf0)
    uint32_t a_addr[2];
    {
        int r = wm + (l & 7) + ((l >> 3) & 1) * 8;
        int ck = (l >> 4) & 1;
#pragma unroll
        for (int mt = 0; mt < 2; mt++) {
            int rr = r + mt * 16;
            int cp = (((rr >> 6) * 4 + ck) ^ (rr & 7));
            a_addr[mt] = cvta_s(As_ + (rr & 63) * 128 + cp * 16);
        }
    }
    // ldmatrix B addrs (stage0)
    uint32_t b_addr[4];
    {
        int n = wn + (l & 7) + ((l >> 4) & 1) * 8;
        int ck = (l >> 3) & 1;
#pragma unroll
        for (int p = 0; p < 4; p++) {
            int nn = n + p * 16;
            int cp = (((nn >> 6) * 4 + ck) ^ (nn & 7));
            b_addr[p] = cvta_s(Bs_ + (nn & 63) * 128 + cp * 16);
        }
    }
    // A STS addrs (buf0) + gmem srcs
    const int fA = tid & 7;
    uint32_t sts_addr[4];
    const float* aload[4];
#pragma unroll
    for (int i = 0; i < 4; i++) {
        int r = i * 32 + (tid >> 3);
        int cp = (((r >> 6) * 4 + (fA >> 1)) ^ (r & 7));
        sts_addr[i] = cvta_s(As_ + (r & 63) * 128 + cp * 16 + (fA & 1) * 8);
        aload[i] = Ab + (size_t)r * KDIM + fA * 4;
    }
    // B cp.async dsts (stage0) + srcs
    uint32_t bst_addr[2];
    const __half* bld[2];
#pragma unroll
    for (int i = 0; i < 2; i++) {
        int cid = tid * 2 + i;
        int n = cid >> 2, c = cid & 3;
        int cp = (((n >> 6) * 4 + c) ^ (n & 7));
        bst_addr[i] = cvta_s(Bs_ + (n & 63) * 128 + cp * 16);
        bld[i] = Bb + (size_t)n * KDIM + c * 8;
    }

    // ---- prologue ----
    float4 pre[2][4];
#pragma unroll
    for (int i = 0; i < 4; i++) pre[0][i] = *(const float4*)(aload[i]);          // A(0)
#pragma unroll
    for (int i = 0; i < 2; i++) CP16(bst_addr[i], bld[i]);                       // B(0)
    asm volatile("cp.async.commit_group;");
#pragma unroll
    for (int i = 0; i < 4; i++) pre[1][i] = *(const float4*)(aload[i] + 32);     // A(1)
#pragma unroll
    for (int i = 0; i < 2; i++) CP16(bst_addr[i] + 8192, bld[i] + 32);           // B(1)
    asm volatile("cp.async.commit_group;");
#pragma unroll
    for (int i = 0; i < 2; i++) CP16(bst_addr[i] + 16384, bld[i] + 64);          // B(2)
    asm volatile("cp.async.commit_group;");

    // STS A(0) into buf0
#pragma unroll
    for (int i = 0; i < 4; i++) {
        __half2 h0 = __floats2half2_rn(pre[0][i].x, pre[0][i].y);
        __half2 h1 = __floats2half2_rn(pre[0][i].z, pre[0][i].w);
        asm volatile("st.shared.v2.b32 [%0], {%1,%2};"
                     :: "r"(sts_addr[i]), "r"(*(uint32_t*)&h0), "r"(*(uint32_t*)&h1));
    }

    float acc[2][8][4];
#pragma unroll
    for (int mt = 0; mt < 2; mt++)
#pragma unroll
        for (int nt = 0; nt < 8; nt++)
#pragma unroll
            for (int i = 0; i < 4; i++) acc[mt][nt][i] = 0.f;

    asm volatile("cp.async.wait_group 2;");   // B(0) resident
    __syncthreads();

    // ---- main loop: at entry of stage kt, A(kt)&B(kt) in smem, A(kt+1) in regs ----
#pragma unroll
    for (int kt = 0; kt < 8; kt++) {
        const uint32_t abuf = (kt & 1) * 8192;
        const uint32_t bbuf = (kt & 3) * 8192;

        // fragments g16=0
        uint32_t a0[2][4];
        LDM4(a0[0][0], a0[0][1], a0[0][2], a0[0][3], a_addr[0] + abuf);
        LDM4(a0[1][0], a0[1][1], a0[1][2], a0[1][3], a_addr[1] + abuf);
        uint32_t bf0[4][4];
#pragma unroll
        for (int p = 0; p < 4; p++)
            LDM4(bf0[p][0], bf0[p][1], bf0[p][2], bf0[p][3], b_addr[p] + bbuf);

        // STS A(kt+1) into the other A buffer (legal: kt-1 readers drained by last sync)
        if (kt < 7) {
            const uint32_t nab = ((kt + 1) & 1) * 8192;
#pragma unroll
            for (int i = 0; i < 4; i++) {
                __half2 h0 = __floats2half2_rn(pre[(kt + 1) & 1][i].x, pre[(kt + 1) & 1][i].y);
                __half2 h1 = __floats2half2_rn(pre[(kt + 1) & 1][i].z, pre[(kt + 1) & 1][i].w);
                asm volatile("st.shared.v2.b32 [%0], {%1,%2};"
                             :: "r"(sts_addr[i] + nab),
                                "r"(*(uint32_t*)&h0), "r"(*(uint32_t*)&h1));
            }
        }

        // fragments g16=1
        uint32_t a1[2][4];
        LDM4(a1[0][0], a1[0][1], a1[0][2], a1[0][3], (a_addr[0] + abuf) ^ 32);
        LDM4(a1[1][0], a1[1][1], a1[1][2], a1[1][3], (a_addr[1] + abuf) ^ 32);
        uint32_t bf1[4][4];
#pragma unroll
        for (int p = 0; p < 4; p++)
            LDM4(bf1[p][0], bf1[p][1], bf1[p][2], bf1[p][3], (b_addr[p] + bbuf) ^ 32);

        // LDG A(kt+2) into freed register buffer
        if (kt < 6) {
#pragma unroll
            for (int i = 0; i < 4; i++)
                pre[kt & 1][i] = *(const float4*)(aload[i] + (kt + 2) * 32);
        }

        // MMA g16=0
#pragma unroll
        for (int nt = 0; nt < 8; nt++) {
            uint32_t q0 = bf0[nt >> 1][(nt & 1) * 2];
            uint32_t q1 = bf0[nt >> 1][(nt & 1) * 2 + 1];
            MMA16(acc[0][nt], a0[0], q0, q1);
            MMA16(acc[1][nt], a0[1], q0, q1);
        }

        // issue B(kt+3); uniform commit
        if (kt < 5) {
            const uint32_t ns = ((kt + 3) & 3) * 8192;
#pragma unroll
            for (int i = 0; i < 2; i++)
                CP16(bst_addr[i] + ns, bld[i] + (kt + 3) * 32);
        }
        asm volatile("cp.async.commit_group;");
        asm volatile("cp.async.wait_group 2;");   // B(kt+1) resident for next stage

        // MMA g16=1
#pragma unroll
        for (int nt = 0; nt < 8; nt++) {
            uint32_t q0 = bf1[nt >> 1][(nt & 1) * 2];
            uint32_t q1 = bf1[nt >> 1][(nt & 1) * 2 + 1];
            MMA16(acc[0][nt], a1[0], q0, q1);
            MMA16(acc[1][nt], a1[1], q0, q1);
        }

        __syncthreads();   // stage boundary: STS(kt+1) visible, readers(kt) drained
    }

    // ---- epilogue: streaming stores ----
#pragma unroll
    for (int mt = 0; mt < 2; mt++) {
        const int r0 = wm + mt * 16 + g;
#pragma unroll
        for (int nt = 0; nt < 8; nt++) {
            const int c = wn + nt * 8 + 2 * t;
            __stcs((float2*)&Cb[(size_t)r0 * 256 + c],
                   make_float2(acc[mt][nt][0], acc[mt][nt][1]));
            __stcs((float2*)&Cb[(size_t)(r0 + 8) * 256 + c],
                   make_float2(acc[mt][nt][2], acc[mt][nt][3]));
        }
    }
}

// ---------------------------------------------------------------------------
extern "C" void kernel_launch(void* const* d_in, const int* in_sizes, int n_in,
                              void* d_out, int out_size)
{
    (void)in_sizes; (void)n_in; (void)out_size;
    const float* queries = (const float*)d_in[0];
    const float* feats   = (const float*)d_in[1];
    const float* W1 = (const float*)d_in[4];
    const float* b1 = (const float*)d_in[5];
    const float* W2 = (const float*)d_in[6];
    const float* b2 = (const float*)d_in[7];
    const float* W3 = (const float*)d_in[8];
    const float* b3 = (const float*)d_in[9];
    const float* W4 = (const float*)d_in[10];
    const float* b4 = (const float*)d_in[11];
    float* out = (float*)d_out;

    __half *wh = nullptr, *qh = nullptr;
    cudaGetSymbolAddress((void**)&wh, g_wh);
    cudaGetSymbolAddress((void**)&qh, g_qh);

    cudaFuncSetAttribute(mlp_fused,   cudaFuncAttributeMaxDynamicSharedMemorySize, MLP_SMEM);
    cudaFuncSetAttribute(gemm_logits, cudaFuncAttributeMaxDynamicSharedMemorySize, LOG_SMEM);

    prep_w<<<256, 256>>>(W1, W2, W3, W4);
    mlp_fused<<<16, 256, MLP_SMEM>>>(queries, wh, b1, b2, b3, b4, qh);
    gemm_logits<<<dim3(2, NF_ / 128, B_), 256, LOG_SMEM>>>(feats, qh, out);
}